// round 2
// baseline (speedup 1.0000x reference)
#include <cuda_runtime.h>
#include <cstdint>
#include <math_constants.h>

constexpr int C  = 128;   // channels
constexpr int KN = 16;    // knn neighbors
constexpr int NMAX = 100000;

// ---------------- device scratch -------------------------------------------
__device__ float g_h0[(size_t)NMAX * C];
__device__ float g_pooled[(size_t)NMAX * C];
__device__ float g_t[(size_t)NMAX * C];
__device__ float g_u[(size_t)NMAX * C];

__device__ float g_sum[4][C];
__device__ float g_sq[4][C];
__device__ float g_scale[4][C];
__device__ float g_shift[4][C];

// ---------------- f32x2 packed helpers --------------------------------------
__device__ __forceinline__ unsigned long long pack2(float lo, float hi) {
    unsigned long long r;
    asm("mov.b64 %0, {%1, %2};" : "=l"(r) : "f"(lo), "f"(hi));
    return r;
}
__device__ __forceinline__ void unpack2(unsigned long long v, float& lo, float& hi) {
    asm("mov.b64 {%0, %1}, %2;" : "=f"(lo), "=f"(hi) : "l"(v));
}
__device__ __forceinline__ void fma2(unsigned long long& d,
                                     unsigned long long a,
                                     unsigned long long b) {
    asm("fma.rn.f32x2 %0, %1, %2, %0;" : "+l"(d) : "l"(a), "l"(b));
}

// ---------------- tiny kernels ----------------------------------------------
__global__ void zero_stats_kernel() {
    int i = threadIdx.x;
    if (i < C) {
        #pragma unroll
        for (int s = 0; s < 4; s++) { g_sum[s][i] = 0.f; g_sq[s][i] = 0.f; }
    }
}

__global__ void finalize_kernel(int s, const float* __restrict__ gamma,
                                const float* __restrict__ beta, float invN) {
    int c = threadIdx.x;
    float mean = g_sum[s][c] * invN;
    float var  = g_sq[s][c] * invN - mean * mean;
    float sc   = gamma[c] * rsqrtf(var + 1e-5f);
    g_scale[s][c] = sc;
    g_shift[s][c] = beta[c] - mean * sc;
}

// ---------------- GEMM: out[n,c] = sum_k A'[n,k] W[k,c] + b[c] ---------------
// MODE 0: A'=A ; MODE 1: A'=bn(A) ; MODE 2: A'=relu(bn(A))
// Block tile 128x128, 256 threads, thread tile 8x8, f32x2 packed FMA.
constexpr int APAD = 132;   // sA row stride (floats), keeps float4 alignment

template <int MODE>
__global__ __launch_bounds__(256, 1)
void gemm_kernel(const float* __restrict__ A,
                 const float* __restrict__ W,
                 const float* __restrict__ bias,
                 float* __restrict__ out,
                 int stat_in, int stat_out, int N) {
    extern __shared__ float smem[];
    float* sW   = smem;                   // [128][128]
    float* sA   = sW + C * C;             // [128][APAD], k-major rows
    float* sSum = sA + 128 * APAD;
    float* sSq  = sSum + C;

    const int tid  = threadIdx.x;
    const int row0 = blockIdx.x * 128;

    for (int i = tid * 4; i < C * C; i += 1024)
        *(float4*)(sW + i) = *(const float4*)(W + i);

    for (int i = tid * 4; i < 128 * C; i += 1024) {
        int r = i >> 7;
        int c = i & (C - 1);
        float4 v = make_float4(0.f, 0.f, 0.f, 0.f);
        int row = row0 + r;
        if (row < N) v = *(const float4*)(A + (size_t)row * C + c);
        if (MODE >= 1) {
            v.x = fmaf(v.x, g_scale[stat_in][c + 0], g_shift[stat_in][c + 0]);
            v.y = fmaf(v.y, g_scale[stat_in][c + 1], g_shift[stat_in][c + 1]);
            v.z = fmaf(v.z, g_scale[stat_in][c + 2], g_shift[stat_in][c + 2]);
            v.w = fmaf(v.w, g_scale[stat_in][c + 3], g_shift[stat_in][c + 3]);
            if (MODE == 2) {
                v.x = fmaxf(v.x, 0.f); v.y = fmaxf(v.y, 0.f);
                v.z = fmaxf(v.z, 0.f); v.w = fmaxf(v.w, 0.f);
            }
        }
        *(float4*)(sA + r * APAD + c) = v;
    }
    if (tid < C) { sSum[tid] = 0.f; sSq[tid] = 0.f; }
    __syncthreads();

    const int tx = tid & 15;   // cols tx*8 .. tx*8+7
    const int ty = tid >> 4;   // rows ty*8 .. ty*8+7

    const float* aBase = sA + ty * 8 * APAD;
    const float* wBase = sW + tx * 8;

    // acc[r][q] = packed pair of (row r, cols 2q / 2q+1)
    unsigned long long acc[8][4];
    #pragma unroll
    for (int r = 0; r < 8; r++)
        #pragma unroll
        for (int q = 0; q < 4; q++) acc[r][q] = 0ull;

    #pragma unroll 1
    for (int k = 0; k < C; k += 4) {
        float4 av[8];
        #pragma unroll
        for (int r = 0; r < 8; r++)
            av[r] = *(const float4*)(aBase + r * APAD + k);

        #pragma unroll
        for (int kk = 0; kk < 4; kk++) {
            const float* wr = wBase + (k + kk) * C;
            float4 w0 = *(const float4*)(wr);
            float4 w1 = *(const float4*)(wr + 4);
            unsigned long long wp[4];
            wp[0] = pack2(w0.x, w0.y);
            wp[1] = pack2(w0.z, w0.w);
            wp[2] = pack2(w1.x, w1.y);
            wp[3] = pack2(w1.z, w1.w);
            #pragma unroll
            for (int r = 0; r < 8; r++) {
                float a = (kk == 0) ? av[r].x : (kk == 1) ? av[r].y
                        : (kk == 2) ? av[r].z : av[r].w;
                unsigned long long ap = pack2(a, a);
                fma2(acc[r][0], ap, wp[0]);
                fma2(acc[r][1], ap, wp[1]);
                fma2(acc[r][2], ap, wp[2]);
                fma2(acc[r][3], ap, wp[3]);
            }
        }
    }

    const int col0 = tx * 8;
    float4 bv0 = *(const float4*)(bias + col0);
    float4 bv1 = *(const float4*)(bias + col0 + 4);
    float bb[8] = {bv0.x, bv0.y, bv0.z, bv0.w, bv1.x, bv1.y, bv1.z, bv1.w};

    float ls[8], lq[8];
    #pragma unroll
    for (int j = 0; j < 8; j++) { ls[j] = 0.f; lq[j] = 0.f; }

    #pragma unroll
    for (int r = 0; r < 8; r++) {
        int row = row0 + ty * 8 + r;
        if (row < N) {
            float o[8];
            #pragma unroll
            for (int q = 0; q < 4; q++) unpack2(acc[r][q], o[2 * q], o[2 * q + 1]);
            #pragma unroll
            for (int j = 0; j < 8; j++) {
                o[j] += bb[j];
                ls[j] += o[j];
                lq[j] += o[j] * o[j];
            }
            float* orow = out + (size_t)row * C + col0;
            *(float4*)(orow)     = make_float4(o[0], o[1], o[2], o[3]);
            *(float4*)(orow + 4) = make_float4(o[4], o[5], o[6], o[7]);
        }
    }

    #pragma unroll
    for (int j = 0; j < 8; j++) {
        atomicAdd(&sSum[col0 + j], ls[j]);
        atomicAdd(&sSq[col0 + j],  lq[j]);
    }
    __syncthreads();
    if (tid < C) {
        atomicAdd(&g_sum[stat_out][tid], sSum[tid]);
        atomicAdd(&g_sq[stat_out][tid],  sSq[tid]);
    }
}

// ---------------- gather + max-pool (vectorized, warp-per-point) -------------
__global__ void gather_kernel(const float* __restrict__ pe,
                              const int* __restrict__ knn,
                              float* __restrict__ pooled, int N) {
    const int lane   = threadIdx.x & 31;
    const int warpId = (blockIdx.x * (blockDim.x >> 5)) + (threadIdx.x >> 5);
    const int nWarps = gridDim.x * (blockDim.x >> 5);
    const int c4     = lane * 4;

    const float4 sc = *(const float4*)(&g_scale[0][c4]);
    const float4 sh = *(const float4*)(&g_shift[0][c4]);

    float4 lsum = make_float4(0.f, 0.f, 0.f, 0.f);
    float4 lsq  = make_float4(0.f, 0.f, 0.f, 0.f);

    for (int n = warpId; n < N; n += nWarps) {
        const int4* ip = (const int4*)(knn + (size_t)n * KN);
        int4 i0 = __ldg(ip + 0), i1 = __ldg(ip + 1);
        int4 i2 = __ldg(ip + 2), i3 = __ldg(ip + 3);
        int idx[16] = { i0.x, i0.y, i0.z, i0.w, i1.x, i1.y, i1.z, i1.w,
                        i2.x, i2.y, i2.z, i2.w, i3.x, i3.y, i3.z, i3.w };

        const float4* peBase = (const float4*)(pe + (((size_t)n * KN) << 7) + c4);
        float4 m = make_float4(-CUDART_INF_F, -CUDART_INF_F,
                               -CUDART_INF_F, -CUDART_INF_F);
        #pragma unroll
        for (int k = 0; k < KN; k++) {
            float4 pv = __ldcs(peBase + k * (C / 4));
            const float4* hp = (const float4*)(g_h0 + (((size_t)idx[k]) << 7) + c4);
            float4 hv = __ldg(hp);
            hv.x = fmaxf(fmaf(hv.x, sc.x, sh.x), 0.f);
            hv.y = fmaxf(fmaf(hv.y, sc.y, sh.y), 0.f);
            hv.z = fmaxf(fmaf(hv.z, sc.z, sh.z), 0.f);
            hv.w = fmaxf(fmaf(hv.w, sc.w, sh.w), 0.f);
            m.x = fmaxf(m.x, pv.x + hv.x);
            m.y = fmaxf(m.y, pv.y + hv.y);
            m.z = fmaxf(m.z, pv.z + hv.z);
            m.w = fmaxf(m.w, pv.w + hv.w);
        }
        *(float4*)(pooled + (((size_t)n) << 7) + c4) = m;
        lsum.x += m.x; lsum.y += m.y; lsum.z += m.z; lsum.w += m.w;
        lsq.x += m.x * m.x; lsq.y += m.y * m.y;
        lsq.z += m.z * m.z; lsq.w += m.w * m.w;
    }

    atomicAdd(&g_sum[1][c4 + 0], lsum.x); atomicAdd(&g_sum[1][c4 + 1], lsum.y);
    atomicAdd(&g_sum[1][c4 + 2], lsum.z); atomicAdd(&g_sum[1][c4 + 3], lsum.w);
    atomicAdd(&g_sq[1][c4 + 0], lsq.x);   atomicAdd(&g_sq[1][c4 + 1], lsq.y);
    atomicAdd(&g_sq[1][c4 + 2], lsq.z);   atomicAdd(&g_sq[1][c4 + 3], lsq.w);
}

// ---------------- residual epilogue ------------------------------------------
__global__ void final_kernel(const float* __restrict__ f,
                             float* __restrict__ out, int N) {
    int i = (blockIdx.x * blockDim.x + threadIdx.x) * 4;
    if (i >= N * C) return;
    int c = i & (C - 1);
    float4 fv = *(const float4*)(f + i);
    float4 uv = *(const float4*)(g_u + i);
    float4 o;
    o.x = fmaxf(fv.x + fmaf(uv.x, g_scale[3][c + 0], g_shift[3][c + 0]), 0.f);
    o.y = fmaxf(fv.y + fmaf(uv.y, g_scale[3][c + 1], g_shift[3][c + 1]), 0.f);
    o.z = fmaxf(fv.z + fmaf(uv.z, g_scale[3][c + 2], g_shift[3][c + 2]), 0.f);
    o.w = fmaxf(fv.w + fmaf(uv.w, g_scale[3][c + 3], g_shift[3][c + 3]), 0.f);
    *(float4*)(out + i) = o;
}

// ---------------- launcher ----------------------------------------------------
extern "C" void kernel_launch(void* const* d_in, const int* in_sizes, int n_in,
                              void* d_out, int out_size) {
    const float* f_in  = (const float*)d_in[1];
    const float* pe    = (const float*)d_in[2];
    const int*   knn   = (const int*)  d_in[3];
    const float* W_pre = (const float*)d_in[4];
    const float* b_pre = (const float*)d_in[5];
    const float* g1    = (const float*)d_in[6];
    const float* be1   = (const float*)d_in[7];
    const float* g2    = (const float*)d_in[8];
    const float* be2   = (const float*)d_in[9];
    const float* W_f1  = (const float*)d_in[10];
    const float* b_f1  = (const float*)d_in[11];
    const float* g3    = (const float*)d_in[12];
    const float* be3   = (const float*)d_in[13];
    const float* W_f2  = (const float*)d_in[14];
    const float* b_f2  = (const float*)d_in[15];
    const float* g4    = (const float*)d_in[16];
    const float* be4   = (const float*)d_in[17];
    float* out = (float*)d_out;

    const int N = in_sizes[0] / 3;
    const float invN = 1.0f / (float)N;

    float *p_h0, *p_pooled, *p_t, *p_u;
    cudaGetSymbolAddress((void**)&p_h0, g_h0);
    cudaGetSymbolAddress((void**)&p_pooled, g_pooled);
    cudaGetSymbolAddress((void**)&p_t, g_t);
    cudaGetSymbolAddress((void**)&p_u, g_u);

    const int SMEM_GEMM = (C * C + 128 * APAD + 2 * C) * (int)sizeof(float);
    cudaFuncSetAttribute(gemm_kernel<0>, cudaFuncAttributeMaxDynamicSharedMemorySize, SMEM_GEMM);
    cudaFuncSetAttribute(gemm_kernel<1>, cudaFuncAttributeMaxDynamicSharedMemorySize, SMEM_GEMM);
    cudaFuncSetAttribute(gemm_kernel<2>, cudaFuncAttributeMaxDynamicSharedMemorySize, SMEM_GEMM);

    const int gemmGrid   = (N + 127) / 128;
    const int gatherGrid = 782;          // 8 warps/block, grid-stride over points
    const int finalGrid  = (N * C / 4 + 255) / 256;

    zero_stats_kernel<<<1, 128>>>();

    gemm_kernel<0><<<gemmGrid, 256, SMEM_GEMM>>>(f_in, W_pre, b_pre, p_h0, 0, 0, N);
    finalize_kernel<<<1, C>>>(0, g1, be1, invN);

    gather_kernel<<<gatherGrid, 256>>>(pe, knn, p_pooled, N);
    finalize_kernel<<<1, C>>>(1, g2, be2, invN);

    gemm_kernel<1><<<gemmGrid, 256, SMEM_GEMM>>>(p_pooled, W_f1, b_f1, p_t, 1, 2, N);
    finalize_kernel<<<1, C>>>(2, g3, be3, invN);

    gemm_kernel<2><<<gemmGrid, 256, SMEM_GEMM>>>(p_t, W_f2, b_f2, p_u, 2, 3, N);
    finalize_kernel<<<1, C>>>(3, g4, be4, invN);

    final_kernel<<<finalGrid, 256>>>(f_in, out, N);
}

// round 3
// speedup vs baseline: 1.6047x; 1.6047x over previous
#include <cuda_runtime.h>
#include <cstdint>
#include <math_constants.h>

constexpr int C  = 128;
constexpr int KN = 16;
constexpr int NMAX = 100000;

// ---------------- device scratch -------------------------------------------
__device__ float g_h0[(size_t)NMAX * C];
__device__ float g_pooled[(size_t)NMAX * C];
__device__ float g_t[(size_t)NMAX * C];
__device__ float g_u[(size_t)NMAX * C];

__device__ float g_sum[4][C];
__device__ float g_sq[4][C];
__device__ float g_scale[4][C];
__device__ float g_shift[4][C];

// ---------------- helpers ----------------------------------------------------
__device__ __forceinline__ uint32_t f2tf32(float x) {
    uint32_t r;
    asm("cvt.rna.tf32.f32 %0, %1;" : "=r"(r) : "f"(x));
    return r;
}

__device__ __forceinline__ void mma_tf32(float* d, const uint32_t* a,
                                         uint32_t b0, uint32_t b1) {
    asm volatile(
        "mma.sync.aligned.m16n8k8.row.col.f32.tf32.tf32.f32 "
        "{%0,%1,%2,%3}, {%4,%5,%6,%7}, {%8,%9}, {%0,%1,%2,%3};"
        : "+f"(d[0]), "+f"(d[1]), "+f"(d[2]), "+f"(d[3])
        : "r"(a[0]), "r"(a[1]), "r"(a[2]), "r"(a[3]), "r"(b0), "r"(b1));
}

// ---------------- tiny kernels ----------------------------------------------
__global__ void zero_stats_kernel() {
    int i = threadIdx.x;
    if (i < C) {
        #pragma unroll
        for (int s = 0; s < 4; s++) { g_sum[s][i] = 0.f; g_sq[s][i] = 0.f; }
    }
}

__global__ void finalize_kernel(int s, const float* __restrict__ gamma,
                                const float* __restrict__ beta, float invN) {
    int c = threadIdx.x;
    float mean = g_sum[s][c] * invN;
    float var  = g_sq[s][c] * invN - mean * mean;
    float sc   = gamma[c] * rsqrtf(var + 1e-5f);
    g_scale[s][c] = sc;
    g_shift[s][c] = beta[c] - mean * sc;
}

// ---------------- tf32 tensor-core GEMM --------------------------------------
// out[n,c] = sum_k A'[n,k] W[k,c] + b[c];  A' per MODE (0: id, 1: bn, 2: relu(bn))
// Block: 256 rows x 128 cols, 256 threads (8 warps x 32 rows).
// smem strides of 136 floats give conflict-free fragment access.
constexpr int PADW = 136;
constexpr int BM   = 256;

template <int MODE>
__global__ __launch_bounds__(256, 1)
void gemm_kernel(const float* __restrict__ A,
                 const float* __restrict__ W,
                 const float* __restrict__ bias,
                 float* __restrict__ out,
                 int stat_in, int stat_out, int N) {
    extern __shared__ float smem[];
    uint32_t* sW  = (uint32_t*)smem;            // [128][136] tf32 bits
    uint32_t* sA  = sW + 128 * PADW;            // [256][136] tf32 bits
    float*    sAf = (float*)sA;                 // reused for output staging
    float*    sSum = (float*)(sA + BM * PADW);
    float*    sSq  = sSum + C;

    const int tid  = threadIdx.x;
    const int row0 = blockIdx.x * BM;

    if (tid < C) { sSum[tid] = 0.f; sSq[tid] = 0.f; }

    // stage W (tf32)
    for (int i = tid * 4; i < C * C; i += 1024) {
        int k = i >> 7, n = i & 127;
        float4 w = *(const float4*)(W + i);
        uint4 t4;
        t4.x = f2tf32(w.x); t4.y = f2tf32(w.y);
        t4.z = f2tf32(w.z); t4.w = f2tf32(w.w);
        *(uint4*)(sW + k * PADW + n) = t4;
    }
    // stage A' (BN transform + tf32)
    for (int i = tid * 4; i < BM * C; i += 1024) {
        int r = i >> 7, c = i & 127;
        int row = row0 + r;
        float4 v = make_float4(0.f, 0.f, 0.f, 0.f);
        if (row < N) v = *(const float4*)(A + (size_t)row * C + c);
        if (MODE >= 1) {
            v.x = fmaf(v.x, g_scale[stat_in][c + 0], g_shift[stat_in][c + 0]);
            v.y = fmaf(v.y, g_scale[stat_in][c + 1], g_shift[stat_in][c + 1]);
            v.z = fmaf(v.z, g_scale[stat_in][c + 2], g_shift[stat_in][c + 2]);
            v.w = fmaf(v.w, g_scale[stat_in][c + 3], g_shift[stat_in][c + 3]);
            if (MODE == 2) {
                v.x = fmaxf(v.x, 0.f); v.y = fmaxf(v.y, 0.f);
                v.z = fmaxf(v.z, 0.f); v.w = fmaxf(v.w, 0.f);
            }
        }
        uint4 t4;
        t4.x = f2tf32(v.x); t4.y = f2tf32(v.y);
        t4.z = f2tf32(v.z); t4.w = f2tf32(v.w);
        *(uint4*)(sA + r * PADW + c) = t4;
    }
    __syncthreads();

    const int warp = tid >> 5, lane = tid & 31;
    const int g = lane >> 2, t = lane & 3;
    const int r0w = warp * 32;

    float d[2][16][4];
    #pragma unroll
    for (int rs = 0; rs < 2; rs++)
        #pragma unroll
        for (int nf = 0; nf < 16; nf++)
            #pragma unroll
            for (int j = 0; j < 4; j++) d[rs][nf][j] = 0.f;

    #pragma unroll 1
    for (int ks = 0; ks < 16; ks++) {
        const int k0 = ks * 8;
        uint32_t a[2][4];
        #pragma unroll
        for (int rs = 0; rs < 2; rs++) {
            const uint32_t* p = sA + (r0w + rs * 16 + g) * PADW + k0 + t;
            a[rs][0] = p[0];
            a[rs][1] = p[8 * PADW];
            a[rs][2] = p[4];
            a[rs][3] = p[8 * PADW + 4];
        }
        const uint32_t* bp = sW + (k0 + t) * PADW + g;
        #pragma unroll
        for (int nf = 0; nf < 16; nf++) {
            uint32_t b0 = bp[nf * 8];
            uint32_t b1 = bp[4 * PADW + nf * 8];
            mma_tf32(d[0][nf], a[0], b0, b1);
            mma_tf32(d[1][nf], a[1], b0, b1);
        }
    }
    __syncthreads();

    // stage results into sAf [256][136]
    #pragma unroll
    for (int rs = 0; rs < 2; rs++) {
        #pragma unroll
        for (int nf = 0; nf < 16; nf++) {
            int row = r0w + rs * 16 + g;
            int col = nf * 8 + 2 * t;
            *(float2*)(sAf + row * PADW + col) =
                make_float2(d[rs][nf][0], d[rs][nf][1]);
            *(float2*)(sAf + (row + 8) * PADW + col) =
                make_float2(d[rs][nf][2], d[rs][nf][3]);
        }
    }
    __syncthreads();

    // coalesced store + bias + stats
    const int c4 = (tid * 4) & 127;
    float4 bv = *(const float4*)(bias + c4);
    float ls0 = 0.f, ls1 = 0.f, ls2 = 0.f, ls3 = 0.f;
    float lq0 = 0.f, lq1 = 0.f, lq2 = 0.f, lq3 = 0.f;
    #pragma unroll 1
    for (int it = 0; it < 32; it++) {
        int r = (tid >> 5) + it * 8;
        int row = row0 + r;
        if (row < N) {
            float4 v = *(float4*)(sAf + r * PADW + c4);
            v.x += bv.x; v.y += bv.y; v.z += bv.z; v.w += bv.w;
            *(float4*)(out + (size_t)row * C + c4) = v;
            ls0 += v.x; ls1 += v.y; ls2 += v.z; ls3 += v.w;
            lq0 += v.x * v.x; lq1 += v.y * v.y;
            lq2 += v.z * v.z; lq3 += v.w * v.w;
        }
    }
    atomicAdd(&sSum[c4 + 0], ls0); atomicAdd(&sSum[c4 + 1], ls1);
    atomicAdd(&sSum[c4 + 2], ls2); atomicAdd(&sSum[c4 + 3], ls3);
    atomicAdd(&sSq[c4 + 0], lq0);  atomicAdd(&sSq[c4 + 1], lq1);
    atomicAdd(&sSq[c4 + 2], lq2);  atomicAdd(&sSq[c4 + 3], lq3);
    __syncthreads();
    if (tid < C) {
        atomicAdd(&g_sum[stat_out][tid], sSum[tid]);
        atomicAdd(&g_sq[stat_out][tid],  sSq[tid]);
    }
}

// ---------------- gather + max-pool (deep MLP batching) ----------------------
__global__ void gather_kernel(const float* __restrict__ pe,
                              const int* __restrict__ knn,
                              float* __restrict__ pooled, int N) {
    const int lane   = threadIdx.x & 31;
    const int warpId = (blockIdx.x * (blockDim.x >> 5)) + (threadIdx.x >> 5);
    const int nWarps = gridDim.x * (blockDim.x >> 5);
    const int c4     = lane * 4;

    const float4 sc = *(const float4*)(&g_scale[0][c4]);
    const float4 sh = *(const float4*)(&g_shift[0][c4]);

    float4 lsum = make_float4(0.f, 0.f, 0.f, 0.f);
    float4 lsq  = make_float4(0.f, 0.f, 0.f, 0.f);

    for (int n = warpId; n < N; n += nWarps) {
        const int4* ip = (const int4*)(knn + (size_t)n * KN);
        int4 i0 = __ldg(ip + 0), i1 = __ldg(ip + 1);
        int4 i2 = __ldg(ip + 2), i3 = __ldg(ip + 3);
        int idx[16] = { i0.x, i0.y, i0.z, i0.w, i1.x, i1.y, i1.z, i1.w,
                        i2.x, i2.y, i2.z, i2.w, i3.x, i3.y, i3.z, i3.w };

        const float4* peBase = (const float4*)(pe + (((size_t)n * KN) << 7) + c4);
        float4 m = make_float4(-CUDART_INF_F, -CUDART_INF_F,
                               -CUDART_INF_F, -CUDART_INF_F);
        #pragma unroll
        for (int half = 0; half < 2; half++) {
            float4 pv[8], hv[8];
            #pragma unroll
            for (int k = 0; k < 8; k++) {
                int kk = half * 8 + k;
                pv[k] = __ldg(peBase + kk * (C / 4));
                hv[k] = __ldg((const float4*)(g_h0 + (((size_t)idx[kk]) << 7) + c4));
            }
            #pragma unroll
            for (int k = 0; k < 8; k++) {
                float4 h = hv[k];
                h.x = fmaxf(fmaf(h.x, sc.x, sh.x), 0.f);
                h.y = fmaxf(fmaf(h.y, sc.y, sh.y), 0.f);
                h.z = fmaxf(fmaf(h.z, sc.z, sh.z), 0.f);
                h.w = fmaxf(fmaf(h.w, sc.w, sh.w), 0.f);
                m.x = fmaxf(m.x, pv[k].x + h.x);
                m.y = fmaxf(m.y, pv[k].y + h.y);
                m.z = fmaxf(m.z, pv[k].z + h.z);
                m.w = fmaxf(m.w, pv[k].w + h.w);
            }
        }
        *(float4*)(pooled + (((size_t)n) << 7) + c4) = m;
        lsum.x += m.x; lsum.y += m.y; lsum.z += m.z; lsum.w += m.w;
        lsq.x += m.x * m.x; lsq.y += m.y * m.y;
        lsq.z += m.z * m.z; lsq.w += m.w * m.w;
    }

    atomicAdd(&g_sum[1][c4 + 0], lsum.x); atomicAdd(&g_sum[1][c4 + 1], lsum.y);
    atomicAdd(&g_sum[1][c4 + 2], lsum.z); atomicAdd(&g_sum[1][c4 + 3], lsum.w);
    atomicAdd(&g_sq[1][c4 + 0], lsq.x);   atomicAdd(&g_sq[1][c4 + 1], lsq.y);
    atomicAdd(&g_sq[1][c4 + 2], lsq.z);   atomicAdd(&g_sq[1][c4 + 3], lsq.w);
}

// ---------------- residual epilogue ------------------------------------------
__global__ void final_kernel(const float* __restrict__ f,
                             float* __restrict__ out, int N) {
    int i = (blockIdx.x * blockDim.x + threadIdx.x) * 4;
    if (i >= N * C) return;
    int c = i & (C - 1);
    float4 fv = *(const float4*)(f + i);
    float4 uv = *(const float4*)(g_u + i);
    float4 o;
    o.x = fmaxf(fv.x + fmaf(uv.x, g_scale[3][c + 0], g_shift[3][c + 0]), 0.f);
    o.y = fmaxf(fv.y + fmaf(uv.y, g_scale[3][c + 1], g_shift[3][c + 1]), 0.f);
    o.z = fmaxf(fv.z + fmaf(uv.z, g_scale[3][c + 2], g_shift[3][c + 2]), 0.f);
    o.w = fmaxf(fv.w + fmaf(uv.w, g_scale[3][c + 3], g_shift[3][c + 3]), 0.f);
    *(float4*)(out + i) = o;
}

// ---------------- launcher ----------------------------------------------------
extern "C" void kernel_launch(void* const* d_in, const int* in_sizes, int n_in,
                              void* d_out, int out_size) {
    const float* f_in  = (const float*)d_in[1];
    const float* pe    = (const float*)d_in[2];
    const int*   knn   = (const int*)  d_in[3];
    const float* W_pre = (const float*)d_in[4];
    const float* b_pre = (const float*)d_in[5];
    const float* g1    = (const float*)d_in[6];
    const float* be1   = (const float*)d_in[7];
    const float* g2    = (const float*)d_in[8];
    const float* be2   = (const float*)d_in[9];
    const float* W_f1  = (const float*)d_in[10];
    const float* b_f1  = (const float*)d_in[11];
    const float* g3    = (const float*)d_in[12];
    const float* be3   = (const float*)d_in[13];
    const float* W_f2  = (const float*)d_in[14];
    const float* b_f2  = (const float*)d_in[15];
    const float* g4    = (const float*)d_in[16];
    const float* be4   = (const float*)d_in[17];
    float* out = (float*)d_out;

    const int N = in_sizes[0] / 3;
    const float invN = 1.0f / (float)N;

    float *p_h0, *p_pooled, *p_t, *p_u;
    cudaGetSymbolAddress((void**)&p_h0, g_h0);
    cudaGetSymbolAddress((void**)&p_pooled, g_pooled);
    cudaGetSymbolAddress((void**)&p_t, g_t);
    cudaGetSymbolAddress((void**)&p_u, g_u);

    const int SMEM_GEMM = (128 * PADW + BM * PADW + 2 * C) * (int)sizeof(float);
    cudaFuncSetAttribute(gemm_kernel<0>, cudaFuncAttributeMaxDynamicSharedMemorySize, SMEM_GEMM);
    cudaFuncSetAttribute(gemm_kernel<1>, cudaFuncAttributeMaxDynamicSharedMemorySize, SMEM_GEMM);
    cudaFuncSetAttribute(gemm_kernel<2>, cudaFuncAttributeMaxDynamicSharedMemorySize, SMEM_GEMM);

    const int gemmGrid   = (N + BM - 1) / BM;
    const int gatherGrid = 592;
    const int finalGrid  = (N * C / 4 + 255) / 256;

    zero_stats_kernel<<<1, 128>>>();

    gemm_kernel<0><<<gemmGrid, 256, SMEM_GEMM>>>(f_in, W_pre, b_pre, p_h0, 0, 0, N);
    finalize_kernel<<<1, C>>>(0, g1, be1, invN);

    gather_kernel<<<gatherGrid, 256>>>(pe, knn, p_pooled, N);
    finalize_kernel<<<1, C>>>(1, g2, be2, invN);

    gemm_kernel<1><<<gemmGrid, 256, SMEM_GEMM>>>(p_pooled, W_f1, b_f1, p_t, 1, 2, N);
    finalize_kernel<<<1, C>>>(2, g3, be3, invN);

    gemm_kernel<2><<<gemmGrid, 256, SMEM_GEMM>>>(p_t, W_f2, b_f2, p_u, 2, 3, N);
    finalize_kernel<<<1, C>>>(3, g4, be4, invN);

    final_kernel<<<finalGrid, 256>>>(f_in, out, N);
}

// round 4
// speedup vs baseline: 1.8311x; 1.1411x over previous
#include <cuda_runtime.h>
#include <cstdint>
#include <math_constants.h>

constexpr int C  = 128;
constexpr int KN = 16;
constexpr int NMAX = 100000;

// ---------------- device scratch -------------------------------------------
__device__ float g_h0[(size_t)NMAX * C];
__device__ float g_pooled[(size_t)NMAX * C];
__device__ float g_t[(size_t)NMAX * C];
__device__ float g_u[(size_t)NMAX * C];

__device__ float g_sum[4][C];
__device__ float g_sq[4][C];
__device__ float g_scale[4][C];
__device__ float g_shift[4][C];

// ---------------- helpers ----------------------------------------------------
__device__ __forceinline__ uint32_t f2tf32(float x) {
    uint32_t r;
    asm("cvt.rna.tf32.f32 %0, %1;" : "=r"(r) : "f"(x));
    return r;
}

__device__ __forceinline__ void mma_tf32(float* d, const uint32_t* a,
                                         uint32_t b0, uint32_t b1) {
    asm volatile(
        "mma.sync.aligned.m16n8k8.row.col.f32.tf32.tf32.f32 "
        "{%0,%1,%2,%3}, {%4,%5,%6,%7}, {%8,%9}, {%0,%1,%2,%3};"
        : "+f"(d[0]), "+f"(d[1]), "+f"(d[2]), "+f"(d[3])
        : "r"(a[0]), "r"(a[1]), "r"(a[2]), "r"(a[3]), "r"(b0), "r"(b1));
}

// ---------------- tiny kernels ----------------------------------------------
__global__ void zero_stats_kernel() {
    int i = threadIdx.x;
    if (i < C) {
        #pragma unroll
        for (int s = 0; s < 4; s++) { g_sum[s][i] = 0.f; g_sq[s][i] = 0.f; }
    }
}

__global__ void finalize_kernel(int s, const float* __restrict__ gamma,
                                const float* __restrict__ beta, float invN) {
    int c = threadIdx.x;
    float mean = g_sum[s][c] * invN;
    float var  = g_sq[s][c] * invN - mean * mean;
    float sc   = gamma[c] * rsqrtf(var + 1e-5f);
    g_scale[s][c] = sc;
    g_shift[s][c] = beta[c] - mean * sc;
}

// ---------------- tf32 tensor-core GEMM --------------------------------------
constexpr int PADW = 136;
constexpr int BM   = 256;

template <int MODE>
__global__ __launch_bounds__(256, 1)
void gemm_kernel(const float* __restrict__ A,
                 const float* __restrict__ W,
                 const float* __restrict__ bias,
                 float* __restrict__ out,
                 int stat_in, int stat_out, int N) {
    extern __shared__ float smem[];
    uint32_t* sW  = (uint32_t*)smem;            // [128][136] tf32 bits
    uint32_t* sA  = sW + 128 * PADW;            // [256][136] tf32 bits
    float*    sAf = (float*)sA;                 // reused for output staging
    float*    sSum = (float*)(sA + BM * PADW);
    float*    sSq  = sSum + C;

    const int tid  = threadIdx.x;
    const int row0 = blockIdx.x * BM;

    if (tid < C) { sSum[tid] = 0.f; sSq[tid] = 0.f; }

    for (int i = tid * 4; i < C * C; i += 1024) {
        int k = i >> 7, n = i & 127;
        float4 w = *(const float4*)(W + i);
        uint4 t4;
        t4.x = f2tf32(w.x); t4.y = f2tf32(w.y);
        t4.z = f2tf32(w.z); t4.w = f2tf32(w.w);
        *(uint4*)(sW + k * PADW + n) = t4;
    }
    for (int i = tid * 4; i < BM * C; i += 1024) {
        int r = i >> 7, c = i & 127;
        int row = row0 + r;
        float4 v = make_float4(0.f, 0.f, 0.f, 0.f);
        if (row < N) v = *(const float4*)(A + (size_t)row * C + c);
        if (MODE >= 1) {
            v.x = fmaf(v.x, g_scale[stat_in][c + 0], g_shift[stat_in][c + 0]);
            v.y = fmaf(v.y, g_scale[stat_in][c + 1], g_shift[stat_in][c + 1]);
            v.z = fmaf(v.z, g_scale[stat_in][c + 2], g_shift[stat_in][c + 2]);
            v.w = fmaf(v.w, g_scale[stat_in][c + 3], g_shift[stat_in][c + 3]);
            if (MODE == 2) {
                v.x = fmaxf(v.x, 0.f); v.y = fmaxf(v.y, 0.f);
                v.z = fmaxf(v.z, 0.f); v.w = fmaxf(v.w, 0.f);
            }
        }
        uint4 t4;
        t4.x = f2tf32(v.x); t4.y = f2tf32(v.y);
        t4.z = f2tf32(v.z); t4.w = f2tf32(v.w);
        *(uint4*)(sA + r * PADW + c) = t4;
    }
    __syncthreads();

    const int warp = tid >> 5, lane = tid & 31;
    const int g = lane >> 2, t = lane & 3;
    const int r0w = warp * 32;

    float d[2][16][4];
    #pragma unroll
    for (int rs = 0; rs < 2; rs++)
        #pragma unroll
        for (int nf = 0; nf < 16; nf++)
            #pragma unroll
            for (int j = 0; j < 4; j++) d[rs][nf][j] = 0.f;

    #pragma unroll 1
    for (int ks = 0; ks < 16; ks++) {
        const int k0 = ks * 8;
        uint32_t a[2][4];
        #pragma unroll
        for (int rs = 0; rs < 2; rs++) {
            const uint32_t* p = sA + (r0w + rs * 16 + g) * PADW + k0 + t;
            a[rs][0] = p[0];
            a[rs][1] = p[8 * PADW];
            a[rs][2] = p[4];
            a[rs][3] = p[8 * PADW + 4];
        }
        const uint32_t* bp = sW + (k0 + t) * PADW + g;
        #pragma unroll
        for (int nf = 0; nf < 16; nf++) {
            uint32_t b0 = bp[nf * 8];
            uint32_t b1 = bp[4 * PADW + nf * 8];
            mma_tf32(d[0][nf], a[0], b0, b1);
            mma_tf32(d[1][nf], a[1], b0, b1);
        }
    }
    __syncthreads();

    #pragma unroll
    for (int rs = 0; rs < 2; rs++) {
        #pragma unroll
        for (int nf = 0; nf < 16; nf++) {
            int row = r0w + rs * 16 + g;
            int col = nf * 8 + 2 * t;
            *(float2*)(sAf + row * PADW + col) =
                make_float2(d[rs][nf][0], d[rs][nf][1]);
            *(float2*)(sAf + (row + 8) * PADW + col) =
                make_float2(d[rs][nf][2], d[rs][nf][3]);
        }
    }
    __syncthreads();

    const int c4 = (tid * 4) & 127;
    float4 bv = *(const float4*)(bias + c4);
    float ls0 = 0.f, ls1 = 0.f, ls2 = 0.f, ls3 = 0.f;
    float lq0 = 0.f, lq1 = 0.f, lq2 = 0.f, lq3 = 0.f;
    #pragma unroll 1
    for (int it = 0; it < 32; it++) {
        int r = (tid >> 5) + it * 8;
        int row = row0 + r;
        if (row < N) {
            float4 v = *(float4*)(sAf + r * PADW + c4);
            v.x += bv.x; v.y += bv.y; v.z += bv.z; v.w += bv.w;
            *(float4*)(out + (size_t)row * C + c4) = v;
            ls0 += v.x; ls1 += v.y; ls2 += v.z; ls3 += v.w;
            lq0 += v.x * v.x; lq1 += v.y * v.y;
            lq2 += v.z * v.z; lq3 += v.w * v.w;
        }
    }
    atomicAdd(&sSum[c4 + 0], ls0); atomicAdd(&sSum[c4 + 1], ls1);
    atomicAdd(&sSum[c4 + 2], ls2); atomicAdd(&sSum[c4 + 3], ls3);
    atomicAdd(&sSq[c4 + 0], lq0);  atomicAdd(&sSq[c4 + 1], lq1);
    atomicAdd(&sSq[c4 + 2], lq2);  atomicAdd(&sSq[c4 + 3], lq3);
    __syncthreads();
    if (tid < C) {
        atomicAdd(&g_sum[stat_out][tid], sSum[tid]);
        atomicAdd(&g_sq[stat_out][tid],  sSq[tid]);
    }
}

// ---------------- gather + max-pool v4 ---------------------------------------
// 2 points per block-iteration; 128 threads per point = 32 chan-groups x 4 k-slots.
// Each thread loads 4 pe float4 + 4 gathered h0 float4 (all independent),
// partial-max over its 4 neighbors, 4-way smem reduction completes the point.
__global__ __launch_bounds__(256)
void gather_kernel(const float* __restrict__ pe,
                   const int* __restrict__ knn,
                   float* __restrict__ pooled, int N) {
    __shared__ float4 sred[2][4][32];

    const int tid = threadIdx.x;
    const int sub = tid >> 7;           // which point within the pair
    const int t   = tid & 127;
    const int cg  = t & 31;             // channel group
    const int c4  = cg * 4;
    const int kg  = t >> 5;             // k-slot 0..3, owns k = kg*4..kg*4+3

    const float4 sc = *(const float4*)(&g_scale[0][c4]);
    const float4 sh = *(const float4*)(&g_shift[0][c4]);

    float4 lsum = make_float4(0.f, 0.f, 0.f, 0.f);
    float4 lsq  = make_float4(0.f, 0.f, 0.f, 0.f);

    const int stride = gridDim.x * 2;
    for (int n = blockIdx.x * 2 + sub; n - sub < N; n += stride) {
        const bool valid = (n < N);
        float4 m = make_float4(-CUDART_INF_F, -CUDART_INF_F,
                               -CUDART_INF_F, -CUDART_INF_F);
        if (valid) {
            int4 idx = __ldg((const int4*)(knn + (size_t)n * KN) + kg);
            const float4* peBase =
                (const float4*)(pe + (((size_t)n * KN + kg * 4) << 7) + c4);
            float4 pv0 = __ldcs(peBase);
            float4 pv1 = __ldcs(peBase + 32);
            float4 pv2 = __ldcs(peBase + 64);
            float4 pv3 = __ldcs(peBase + 96);
            float4 h0 = __ldg((const float4*)(g_h0 + (((size_t)idx.x) << 7) + c4));
            float4 h1 = __ldg((const float4*)(g_h0 + (((size_t)idx.y) << 7) + c4));
            float4 h2 = __ldg((const float4*)(g_h0 + (((size_t)idx.z) << 7) + c4));
            float4 h3 = __ldg((const float4*)(g_h0 + (((size_t)idx.w) << 7) + c4));

            #define GMAX(pv, hv)                                              \
            {                                                                 \
                float4 h = hv;                                                \
                h.x = fmaxf(fmaf(h.x, sc.x, sh.x), 0.f);                      \
                h.y = fmaxf(fmaf(h.y, sc.y, sh.y), 0.f);                      \
                h.z = fmaxf(fmaf(h.z, sc.z, sh.z), 0.f);                      \
                h.w = fmaxf(fmaf(h.w, sc.w, sh.w), 0.f);                      \
                m.x = fmaxf(m.x, pv.x + h.x);                                 \
                m.y = fmaxf(m.y, pv.y + h.y);                                 \
                m.z = fmaxf(m.z, pv.z + h.z);                                 \
                m.w = fmaxf(m.w, pv.w + h.w);                                 \
            }
            GMAX(pv0, h0) GMAX(pv1, h1) GMAX(pv2, h2) GMAX(pv3, h3)
            #undef GMAX
        }
        sred[sub][kg][cg] = m;
        __syncthreads();
        if (kg == 0 && valid) {
            float4 a = sred[sub][0][cg], b = sred[sub][1][cg];
            float4 cc = sred[sub][2][cg], dd = sred[sub][3][cg];
            m.x = fmaxf(fmaxf(a.x, b.x), fmaxf(cc.x, dd.x));
            m.y = fmaxf(fmaxf(a.y, b.y), fmaxf(cc.y, dd.y));
            m.z = fmaxf(fmaxf(a.z, b.z), fmaxf(cc.z, dd.z));
            m.w = fmaxf(fmaxf(a.w, b.w), fmaxf(cc.w, dd.w));
            *(float4*)(pooled + (((size_t)n) << 7) + c4) = m;
            lsum.x += m.x; lsum.y += m.y; lsum.z += m.z; lsum.w += m.w;
            lsq.x += m.x * m.x; lsq.y += m.y * m.y;
            lsq.z += m.z * m.z; lsq.w += m.w * m.w;
        }
        __syncthreads();
    }

    if (kg == 0) {
        atomicAdd(&g_sum[1][c4 + 0], lsum.x); atomicAdd(&g_sum[1][c4 + 1], lsum.y);
        atomicAdd(&g_sum[1][c4 + 2], lsum.z); atomicAdd(&g_sum[1][c4 + 3], lsum.w);
        atomicAdd(&g_sq[1][c4 + 0], lsq.x);   atomicAdd(&g_sq[1][c4 + 1], lsq.y);
        atomicAdd(&g_sq[1][c4 + 2], lsq.z);   atomicAdd(&g_sq[1][c4 + 3], lsq.w);
    }
}

// ---------------- residual epilogue ------------------------------------------
__global__ void final_kernel(const float* __restrict__ f,
                             float* __restrict__ out, int N) {
    int i = (blockIdx.x * blockDim.x + threadIdx.x) * 4;
    if (i >= N * C) return;
    int c = i & (C - 1);
    float4 fv = *(const float4*)(f + i);
    float4 uv = *(const float4*)(g_u + i);
    float4 o;
    o.x = fmaxf(fv.x + fmaf(uv.x, g_scale[3][c + 0], g_shift[3][c + 0]), 0.f);
    o.y = fmaxf(fv.y + fmaf(uv.y, g_scale[3][c + 1], g_shift[3][c + 1]), 0.f);
    o.z = fmaxf(fv.z + fmaf(uv.z, g_scale[3][c + 2], g_shift[3][c + 2]), 0.f);
    o.w = fmaxf(fv.w + fmaf(uv.w, g_scale[3][c + 3], g_shift[3][c + 3]), 0.f);
    *(float4*)(out + i) = o;
}

// ---------------- launcher ----------------------------------------------------
extern "C" void kernel_launch(void* const* d_in, const int* in_sizes, int n_in,
                              void* d_out, int out_size) {
    const float* f_in  = (const float*)d_in[1];
    const float* pe    = (const float*)d_in[2];
    const int*   knn   = (const int*)  d_in[3];
    const float* W_pre = (const float*)d_in[4];
    const float* b_pre = (const float*)d_in[5];
    const float* g1    = (const float*)d_in[6];
    const float* be1   = (const float*)d_in[7];
    const float* g2    = (const float*)d_in[8];
    const float* be2   = (const float*)d_in[9];
    const float* W_f1  = (const float*)d_in[10];
    const float* b_f1  = (const float*)d_in[11];
    const float* g3    = (const float*)d_in[12];
    const float* be3   = (const float*)d_in[13];
    const float* W_f2  = (const float*)d_in[14];
    const float* b_f2  = (const float*)d_in[15];
    const float* g4    = (const float*)d_in[16];
    const float* be4   = (const float*)d_in[17];
    float* out = (float*)d_out;

    const int N = in_sizes[0] / 3;
    const float invN = 1.0f / (float)N;

    float *p_h0, *p_pooled, *p_t, *p_u;
    cudaGetSymbolAddress((void**)&p_h0, g_h0);
    cudaGetSymbolAddress((void**)&p_pooled, g_pooled);
    cudaGetSymbolAddress((void**)&p_t, g_t);
    cudaGetSymbolAddress((void**)&p_u, g_u);

    const int SMEM_GEMM = (128 * PADW + BM * PADW + 2 * C) * (int)sizeof(float);
    cudaFuncSetAttribute(gemm_kernel<0>, cudaFuncAttributeMaxDynamicSharedMemorySize, SMEM_GEMM);
    cudaFuncSetAttribute(gemm_kernel<1>, cudaFuncAttributeMaxDynamicSharedMemorySize, SMEM_GEMM);
    cudaFuncSetAttribute(gemm_kernel<2>, cudaFuncAttributeMaxDynamicSharedMemorySize, SMEM_GEMM);

    const int gemmGrid   = (N + BM - 1) / BM;
    const int gatherGrid = 1184;      // 2 points / block-iter, grid-stride
    const int finalGrid  = (N * C / 4 + 255) / 256;

    zero_stats_kernel<<<1, 128>>>();

    gemm_kernel<0><<<gemmGrid, 256, SMEM_GEMM>>>(f_in, W_pre, b_pre, p_h0, 0, 0, N);
    finalize_kernel<<<1, C>>>(0, g1, be1, invN);

    gather_kernel<<<gatherGrid, 256>>>(pe, knn, p_pooled, N);
    finalize_kernel<<<1, C>>>(1, g2, be2, invN);

    gemm_kernel<1><<<gemmGrid, 256, SMEM_GEMM>>>(p_pooled, W_f1, b_f1, p_t, 1, 2, N);
    finalize_kernel<<<1, C>>>(2, g3, be3, invN);

    gemm_kernel<2><<<gemmGrid, 256, SMEM_GEMM>>>(p_t, W_f2, b_f2, p_u, 2, 3, N);
    finalize_kernel<<<1, C>>>(3, g4, be4, invN);

    final_kernel<<<finalGrid, 256>>>(f_in, out, N);
}

// round 6
// speedup vs baseline: 1.8495x; 1.0101x over previous
#include <cuda_runtime.h>
#include <cstdint>
#include <math_constants.h>

constexpr int C  = 128;
constexpr int KN = 16;
constexpr int NMAX = 100000;

// ---------------- device scratch -------------------------------------------
__device__ float g_h0[(size_t)NMAX * C];
__device__ float g_pooled[(size_t)NMAX * C];
__device__ float g_t[(size_t)NMAX * C];
__device__ float g_u[(size_t)NMAX * C];

__device__ float g_sum[4][C];
__device__ float g_sq[4][C];
__device__ float g_scale[4][C];
__device__ float g_shift[4][C];

// ---------------- helpers ----------------------------------------------------
__device__ __forceinline__ uint32_t f2tf32(float x) {
    uint32_t r;
    asm("cvt.rna.tf32.f32 %0, %1;" : "=r"(r) : "f"(x));
    return r;
}

__device__ __forceinline__ void mma_tf32(float* d, const uint32_t* a,
                                         uint32_t b0, uint32_t b1) {
    asm volatile(
        "mma.sync.aligned.m16n8k8.row.col.f32.tf32.tf32.f32 "
        "{%0,%1,%2,%3}, {%4,%5,%6,%7}, {%8,%9}, {%0,%1,%2,%3};"
        : "+f"(d[0]), "+f"(d[1]), "+f"(d[2]), "+f"(d[3])
        : "r"(a[0]), "r"(a[1]), "r"(a[2]), "r"(a[3]), "r"(b0), "r"(b1));
}

// ---------------- tiny kernels ----------------------------------------------
__global__ void zero_stats_kernel() {
    int i = threadIdx.x;
    if (i < C) {
        #pragma unroll
        for (int s = 0; s < 4; s++) { g_sum[s][i] = 0.f; g_sq[s][i] = 0.f; }
    }
}

__global__ void finalize_kernel(int s, const float* __restrict__ gamma,
                                const float* __restrict__ beta, float invN) {
    int c = threadIdx.x;
    float mean = g_sum[s][c] * invN;
    float var  = g_sq[s][c] * invN - mean * mean;
    float sc   = gamma[c] * rsqrtf(var + 1e-5f);
    g_scale[s][c] = sc;
    g_shift[s][c] = beta[c] - mean * sc;
}

// ---------------- tf32 tensor-core GEMM --------------------------------------
constexpr int PADW = 136;
constexpr int BM   = 256;

template <int MODE>
__global__ __launch_bounds__(256, 1)
void gemm_kernel(const float* __restrict__ A,
                 const float* __restrict__ W,
                 const float* __restrict__ bias,
                 float* __restrict__ out,
                 int stat_in, int stat_out, int N) {
    extern __shared__ float smem[];
    uint32_t* sW  = (uint32_t*)smem;            // [128][136] tf32 bits
    uint32_t* sA  = sW + 128 * PADW;            // [256][136] tf32 bits
    float*    sAf = (float*)sA;                 // reused for output staging
    float*    sSum = (float*)(sA + BM * PADW);
    float*    sSq  = sSum + C;

    const int tid  = threadIdx.x;
    const int row0 = blockIdx.x * BM;

    if (tid < C) { sSum[tid] = 0.f; sSq[tid] = 0.f; }

    for (int i = tid * 4; i < C * C; i += 1024) {
        int k = i >> 7, n = i & 127;
        float4 w = *(const float4*)(W + i);
        uint4 t4;
        t4.x = f2tf32(w.x); t4.y = f2tf32(w.y);
        t4.z = f2tf32(w.z); t4.w = f2tf32(w.w);
        *(uint4*)(sW + k * PADW + n) = t4;
    }
    for (int i = tid * 4; i < BM * C; i += 1024) {
        int r = i >> 7, c = i & 127;
        int row = row0 + r;
        float4 v = make_float4(0.f, 0.f, 0.f, 0.f);
        if (row < N) v = *(const float4*)(A + (size_t)row * C + c);
        if (MODE >= 1) {
            v.x = fmaf(v.x, g_scale[stat_in][c + 0], g_shift[stat_in][c + 0]);
            v.y = fmaf(v.y, g_scale[stat_in][c + 1], g_shift[stat_in][c + 1]);
            v.z = fmaf(v.z, g_scale[stat_in][c + 2], g_shift[stat_in][c + 2]);
            v.w = fmaf(v.w, g_scale[stat_in][c + 3], g_shift[stat_in][c + 3]);
            if (MODE == 2) {
                v.x = fmaxf(v.x, 0.f); v.y = fmaxf(v.y, 0.f);
                v.z = fmaxf(v.z, 0.f); v.w = fmaxf(v.w, 0.f);
            }
        }
        uint4 t4;
        t4.x = f2tf32(v.x); t4.y = f2tf32(v.y);
        t4.z = f2tf32(v.z); t4.w = f2tf32(v.w);
        *(uint4*)(sA + r * PADW + c) = t4;
    }
    __syncthreads();

    const int warp = tid >> 5, lane = tid & 31;
    const int g = lane >> 2, t = lane & 3;
    const int r0w = warp * 32;

    float d[2][16][4];
    #pragma unroll
    for (int rs = 0; rs < 2; rs++)
        #pragma unroll
        for (int nf = 0; nf < 16; nf++)
            #pragma unroll
            for (int j = 0; j < 4; j++) d[rs][nf][j] = 0.f;

    #pragma unroll 1
    for (int ks = 0; ks < 16; ks++) {
        const int k0 = ks * 8;
        uint32_t a[2][4];
        #pragma unroll
        for (int rs = 0; rs < 2; rs++) {
            const uint32_t* p = sA + (r0w + rs * 16 + g) * PADW + k0 + t;
            a[rs][0] = p[0];
            a[rs][1] = p[8 * PADW];
            a[rs][2] = p[4];
            a[rs][3] = p[8 * PADW + 4];
        }
        const uint32_t* bp = sW + (k0 + t) * PADW + g;
        #pragma unroll
        for (int nf = 0; nf < 16; nf++) {
            uint32_t b0 = bp[nf * 8];
            uint32_t b1 = bp[4 * PADW + nf * 8];
            mma_tf32(d[0][nf], a[0], b0, b1);
            mma_tf32(d[1][nf], a[1], b0, b1);
        }
    }
    __syncthreads();

    #pragma unroll
    for (int rs = 0; rs < 2; rs++) {
        #pragma unroll
        for (int nf = 0; nf < 16; nf++) {
            int row = r0w + rs * 16 + g;
            int col = nf * 8 + 2 * t;
            *(float2*)(sAf + row * PADW + col) =
                make_float2(d[rs][nf][0], d[rs][nf][1]);
            *(float2*)(sAf + (row + 8) * PADW + col) =
                make_float2(d[rs][nf][2], d[rs][nf][3]);
        }
    }
    __syncthreads();

    const int c4 = (tid * 4) & 127;
    float4 bv = *(const float4*)(bias + c4);
    float ls0 = 0.f, ls1 = 0.f, ls2 = 0.f, ls3 = 0.f;
    float lq0 = 0.f, lq1 = 0.f, lq2 = 0.f, lq3 = 0.f;
    #pragma unroll 1
    for (int it = 0; it < 32; it++) {
        int r = (tid >> 5) + it * 8;
        int row = row0 + r;
        if (row < N) {
            float4 v = *(float4*)(sAf + r * PADW + c4);
            v.x += bv.x; v.y += bv.y; v.z += bv.z; v.w += bv.w;
            *(float4*)(out + (size_t)row * C + c4) = v;
            ls0 += v.x; ls1 += v.y; ls2 += v.z; ls3 += v.w;
            lq0 += v.x * v.x; lq1 += v.y * v.y;
            lq2 += v.z * v.z; lq3 += v.w * v.w;
        }
    }
    atomicAdd(&sSum[c4 + 0], ls0); atomicAdd(&sSum[c4 + 1], ls1);
    atomicAdd(&sSum[c4 + 2], ls2); atomicAdd(&sSum[c4 + 3], ls3);
    atomicAdd(&sSq[c4 + 0], lq0);  atomicAdd(&sSq[c4 + 1], lq1);
    atomicAdd(&sSq[c4 + 2], lq2);  atomicAdd(&sSq[c4 + 3], lq3);
    __syncthreads();
    if (tid < C) {
        atomicAdd(&g_sum[stat_out][tid], sSum[tid]);
        atomicAdd(&g_sq[stat_out][tid],  sSq[tid]);
    }
}

// ---------------- gather + max-pool v5 (barrier-free, shfl reduce) -----------
// 4 warps per point; each warp owns a 32-channel block.
// Lane = kg*8 + cg: kg in 0..3 owns neighbors kg*4..kg*4+3, cg*4 = channel off.
// 8 independent loads per lane, warp-local bfly-max over kg, no __syncthreads.
__global__ __launch_bounds__(256)
void gather_kernel(const float* __restrict__ pe,
                   const int* __restrict__ knn,
                   float* __restrict__ pooled, int N) {
    const int w    = (blockIdx.x * blockDim.x + threadIdx.x) >> 5;
    const int lane = threadIdx.x & 31;
    const int kg   = lane >> 3;            // 0..3
    const int cg   = lane & 7;             // 0..7
    const int c4   = (w & 3) * 32 + cg * 4;
    const int nGroups = (gridDim.x * blockDim.x) >> 7;

    const float4 sc = *(const float4*)(&g_scale[0][c4]);
    const float4 sh = *(const float4*)(&g_shift[0][c4]);

    float4 lsum = make_float4(0.f, 0.f, 0.f, 0.f);
    float4 lsq  = make_float4(0.f, 0.f, 0.f, 0.f);

    for (int n = (w >> 2); n < N; n += nGroups) {
        int4 idx = __ldg((const int4*)(knn + (size_t)n * KN) + kg);
        const float4* peBase =
            (const float4*)(pe + (((size_t)n * KN + kg * 4) << 7) + c4);
        float4 pv0 = __ldcs(peBase);
        float4 pv1 = __ldcs(peBase + 32);
        float4 pv2 = __ldcs(peBase + 64);
        float4 pv3 = __ldcs(peBase + 96);
        float4 h0 = __ldg((const float4*)(g_h0 + (((size_t)idx.x) << 7) + c4));
        float4 h1 = __ldg((const float4*)(g_h0 + (((size_t)idx.y) << 7) + c4));
        float4 h2 = __ldg((const float4*)(g_h0 + (((size_t)idx.z) << 7) + c4));
        float4 h3 = __ldg((const float4*)(g_h0 + (((size_t)idx.w) << 7) + c4));

        float4 m = make_float4(-CUDART_INF_F, -CUDART_INF_F,
                               -CUDART_INF_F, -CUDART_INF_F);
        #define GMAX(pv, hv)                                              \
        {                                                                 \
            float4 h = hv;                                                \
            h.x = fmaxf(fmaf(h.x, sc.x, sh.x), 0.f);                      \
            h.y = fmaxf(fmaf(h.y, sc.y, sh.y), 0.f);                      \
            h.z = fmaxf(fmaf(h.z, sc.z, sh.z), 0.f);                      \
            h.w = fmaxf(fmaf(h.w, sc.w, sh.w), 0.f);                      \
            m.x = fmaxf(m.x, pv.x + h.x);                                 \
            m.y = fmaxf(m.y, pv.y + h.y);                                 \
            m.z = fmaxf(m.z, pv.z + h.z);                                 \
            m.w = fmaxf(m.w, pv.w + h.w);                                 \
        }
        GMAX(pv0, h0) GMAX(pv1, h1) GMAX(pv2, h2) GMAX(pv3, h3)
        #undef GMAX

        // warp-local max over the 4 k-slots (lanes differing in bits 3,4)
        m.x = fmaxf(m.x, __shfl_xor_sync(0xffffffffu, m.x, 8));
        m.y = fmaxf(m.y, __shfl_xor_sync(0xffffffffu, m.y, 8));
        m.z = fmaxf(m.z, __shfl_xor_sync(0xffffffffu, m.z, 8));
        m.w = fmaxf(m.w, __shfl_xor_sync(0xffffffffu, m.w, 8));
        m.x = fmaxf(m.x, __shfl_xor_sync(0xffffffffu, m.x, 16));
        m.y = fmaxf(m.y, __shfl_xor_sync(0xffffffffu, m.y, 16));
        m.z = fmaxf(m.z, __shfl_xor_sync(0xffffffffu, m.z, 16));
        m.w = fmaxf(m.w, __shfl_xor_sync(0xffffffffu, m.w, 16));

        if (kg == 0) {
            *(float4*)(pooled + (((size_t)n) << 7) + c4) = m;
            lsum.x += m.x; lsum.y += m.y; lsum.z += m.z; lsum.w += m.w;
            lsq.x += m.x * m.x; lsq.y += m.y * m.y;
            lsq.z += m.z * m.z; lsq.w += m.w * m.w;
        }
    }

    if (kg == 0) {
        atomicAdd(&g_sum[1][c4 + 0], lsum.x); atomicAdd(&g_sum[1][c4 + 1], lsum.y);
        atomicAdd(&g_sum[1][c4 + 2], lsum.z); atomicAdd(&g_sum[1][c4 + 3], lsum.w);
        atomicAdd(&g_sq[1][c4 + 0], lsq.x);   atomicAdd(&g_sq[1][c4 + 1], lsq.y);
        atomicAdd(&g_sq[1][c4 + 2], lsq.z);   atomicAdd(&g_sq[1][c4 + 3], lsq.w);
    }
}

// ---------------- residual epilogue ------------------------------------------
__global__ void final_kernel(const float* __restrict__ f,
                             float* __restrict__ out, int N) {
    int i = (blockIdx.x * blockDim.x + threadIdx.x) * 4;
    if (i >= N * C) return;
    int c = i & (C - 1);
    float4 fv = *(const float4*)(f + i);
    float4 uv = *(const float4*)(g_u + i);
    float4 o;
    o.x = fmaxf(fv.x + fmaf(uv.x, g_scale[3][c + 0], g_shift[3][c + 0]), 0.f);
    o.y = fmaxf(fv.y + fmaf(uv.y, g_scale[3][c + 1], g_shift[3][c + 1]), 0.f);
    o.z = fmaxf(fv.z + fmaf(uv.z, g_scale[3][c + 2], g_shift[3][c + 2]), 0.f);
    o.w = fmaxf(fv.w + fmaf(uv.w, g_scale[3][c + 3], g_shift[3][c + 3]), 0.f);
    *(float4*)(out + i) = o;
}

// ---------------- launcher ----------------------------------------------------
extern "C" void kernel_launch(void* const* d_in, const int* in_sizes, int n_in,
                              void* d_out, int out_size) {
    const float* f_in  = (const float*)d_in[1];
    const float* pe    = (const float*)d_in[2];
    const int*   knn   = (const int*)  d_in[3];
    const float* W_pre = (const float*)d_in[4];
    const float* b_pre = (const float*)d_in[5];
    const float* g1    = (const float*)d_in[6];
    const float* be1   = (const float*)d_in[7];
    const float* g2    = (const float*)d_in[8];
    const float* be2   = (const float*)d_in[9];
    const float* W_f1  = (const float*)d_in[10];
    const float* b_f1  = (const float*)d_in[11];
    const float* g3    = (const float*)d_in[12];
    const float* be3   = (const float*)d_in[13];
    const float* W_f2  = (const float*)d_in[14];
    const float* b_f2  = (const float*)d_in[15];
    const float* g4    = (const float*)d_in[16];
    const float* be4   = (const float*)d_in[17];
    float* out = (float*)d_out;

    const int N = in_sizes[0] / 3;
    const float invN = 1.0f / (float)N;

    float *p_h0, *p_pooled, *p_t, *p_u;
    cudaGetSymbolAddress((void**)&p_h0, g_h0);
    cudaGetSymbolAddress((void**)&p_pooled, g_pooled);
    cudaGetSymbolAddress((void**)&p_t, g_t);
    cudaGetSymbolAddress((void**)&p_u, g_u);

    const int SMEM_GEMM = (128 * PADW + BM * PADW + 2 * C) * (int)sizeof(float);
    cudaFuncSetAttribute(gemm_kernel<0>, cudaFuncAttributeMaxDynamicSharedMemorySize, SMEM_GEMM);
    cudaFuncSetAttribute(gemm_kernel<1>, cudaFuncAttributeMaxDynamicSharedMemorySize, SMEM_GEMM);
    cudaFuncSetAttribute(gemm_kernel<2>, cudaFuncAttributeMaxDynamicSharedMemorySize, SMEM_GEMM);

    const int gemmGrid   = (N + BM - 1) / BM;
    const int gatherGrid = 1184;      // 8 warps/block -> 2368 point-groups
    const int finalGrid  = (N * C / 4 + 255) / 256;

    zero_stats_kernel<<<1, 128>>>();

    gemm_kernel<0><<<gemmGrid, 256, SMEM_GEMM>>>(f_in, W_pre, b_pre, p_h0, 0, 0, N);
    finalize_kernel<<<1, C>>>(0, g1, be1, invN);

    gather_kernel<<<gatherGrid, 256>>>(pe, knn, p_pooled, N);
    finalize_kernel<<<1, C>>>(1, g2, be2, invN);

    gemm_kernel<1><<<gemmGrid, 256, SMEM_GEMM>>>(p_pooled, W_f1, b_f1, p_t, 1, 2, N);
    finalize_kernel<<<1, C>>>(2, g3, be3, invN);

    gemm_kernel<2><<<gemmGrid, 256, SMEM_GEMM>>>(p_t, W_f2, b_f2, p_u, 2, 3, N);
    finalize_kernel<<<1, C>>>(3, g4, be4, invN);

    final_kernel<<<finalGrid, 256>>>(f_in, out, N);
}